// round 1
// baseline (speedup 1.0000x reference)
#include <cuda_runtime.h>

// Problem constants
#define NB   16
#define CIN  256
#define LL   300
#define VV   25
#define PP   3
#define COUT 256
#define KDIM (PP*CIN)        // 768
#define NCOL (NB*LL*VV)      // 120000
#define COLS_PER_N (LL*VV)   // 7500

// Scratch (device globals; no runtime allocation allowed)
__device__ float g_u[KDIM * NCOL];       // 768 x 120000  (~368 MB)
__device__ float g_z[COUT * NCOL];       // 256 x 120000  (~123 MB)
__device__ float g_Wall[COUT * KDIM];    // 256 x 768
__device__ float g_Aw[PP * VV * VV];
__device__ float g_bias2[COUT * VV];

// ---------------------------------------------------------------------------
// Prep: Wall[c][p*256+ci] = conv_w[(p*256+c)*256+ci];  Aw = A * edge_importance;
// bias2[c][w] = sum_p b_p[c] * sum_v Aw_p[v][w]
// ---------------------------------------------------------------------------
__global__ void prep_kernel(const float* __restrict__ A,
                            const float* __restrict__ conv_w,
                            const float* __restrict__ conv_b,
                            const float* __restrict__ ei) {
    int idx = blockIdx.x * blockDim.x + threadIdx.x;
    if (idx < COUT * KDIM) {
        int c = idx / KDIM, k = idx % KDIM;
        int p = k >> 8, ci = k & 255;
        g_Wall[idx] = conv_w[((p << 8) + c) * CIN + ci];
    }
    if (idx < PP * VV * VV) {
        g_Aw[idx] = A[idx] * ei[idx];
    }
    if (idx < COUT * VV) {
        int c = idx / VV, w = idx % VV;
        float s = 0.f;
        for (int p = 0; p < PP; ++p) {
            float b = conv_b[(p << 8) + c];
            for (int v = 0; v < VV; ++v) {
                int a = (p * VV + v) * VV + w;
                s += b * A[a] * ei[a];
            }
        }
        g_bias2[idx] = s;
    }
}

// ---------------------------------------------------------------------------
// u kernel: one block per (n, ci).
// Phase 1: sliding 9-tap window sum over l into smem xt[m][v] (padded row 28).
// Phase 2: u_p[ci][n,m,w] = sum_v xt[m][v] * Aw_p[v][w]
// ---------------------------------------------------------------------------
__global__ __launch_bounds__(256) void u_kernel(const float* __restrict__ x) {
    __shared__ __align__(16) float xt[LL * 28];
    const int n = blockIdx.y;
    const int ci = blockIdx.x;
    const float* __restrict__ xr = x + ((size_t)(n * CIN + ci)) * (LL * VV);
    const int t = threadIdx.x;

    // Phase 1: 250 threads = 25 v-lanes x 10 m-chunks of 30 frames
    if (t < 250) {
        int v = t % 25;
        int mi = t / 25;
        int m0 = mi * 30;
        float s = 0.f;
        int lstart = m0 - 8; if (lstart < 0) lstart = 0;
        for (int l = lstart; l < m0; ++l) s += xr[l * VV + v];
        for (int m = m0; m < m0 + 30; ++m) {
            s += xr[m * VV + v];
            xt[m * 28 + v] = s;
            if (m >= 8) s -= xr[(m - 8) * VV + v];
        }
    }
    __syncthreads();

    // Phase 2: warp = one m-residue class; lanes 0..24 = w
    const int w = t & 31;
    const int mg = t >> 5;   // 0..7
    if (w < 25) {
        for (int p = 0; p < PP; ++p) {
            float aw[25];
#pragma unroll
            for (int v = 0; v < 25; ++v) aw[v] = g_Aw[(p * VV + v) * VV + w];
            float* __restrict__ ubase = g_u + ((p << 8) + ci) * NCOL + n * COLS_PER_N;
            for (int m = mg; m < LL; m += 8) {
                const float4* xv4 = (const float4*)(xt + m * 28);
                float acc = 0.f;
#pragma unroll
                for (int q = 0; q < 6; ++q) {
                    float4 xv = xv4[q];
                    acc += xv.x * aw[4 * q + 0];
                    acc += xv.y * aw[4 * q + 1];
                    acc += xv.z * aw[4 * q + 2];
                    acc += xv.w * aw[4 * q + 3];
                }
                acc += xt[m * 28 + 24] * aw[24];
                ubase[m * VV + w] = acc;
            }
        }
    }
}

// ---------------------------------------------------------------------------
// GEMM: z[256 x 120000] = Wall[256 x 768] @ u[768 x 120000]  (+ bias term)
// 128x128 CTA tile, BK=8, 8x8 per-thread microtile, double-buffered smem.
// ---------------------------------------------------------------------------
#define BM 128
#define BN 128
#define BK 8
#define NKCH (KDIM / BK)   // 96

__global__ __launch_bounds__(256) void gemm_kernel() {
    __shared__ __align__(16) float As[2][BK][BM];
    __shared__ __align__(16) float Bs[2][BK][BN];

    const int tid = threadIdx.x;
    const int tx = tid % 16;
    const int ty = tid / 16;
    const int col0 = blockIdx.x * BN;
    const int row0 = blockIdx.y * BM;

    const float* __restrict__ Ag = g_Wall;
    const float* __restrict__ Bg = g_u;

    float acc[8][8];
#pragma unroll
    for (int i = 0; i < 8; ++i)
#pragma unroll
        for (int j = 0; j < 8; ++j) acc[i][j] = 0.f;

    // load mapping (one float4 per thread per tile)
    const int a_row = tid >> 1;            // 0..127
    const int a_kq  = (tid & 1) * 4;       // 0 or 4
    const int b_krow = tid >> 5;           // 0..7
    const int b_cq   = (tid & 31) * 4;     // 0..124
    const int bcol = col0 + b_cq;
    const bool bvalid = (bcol < NCOL);

    // prefetch chunk 0
    float4 a_reg = *(const float4*)(Ag + (row0 + a_row) * KDIM + a_kq);
    float4 b_reg = make_float4(0.f, 0.f, 0.f, 0.f);
    if (bvalid) b_reg = *(const float4*)(Bg + b_krow * NCOL + bcol);

    As[0][a_kq + 0][a_row] = a_reg.x;
    As[0][a_kq + 1][a_row] = a_reg.y;
    As[0][a_kq + 2][a_row] = a_reg.z;
    As[0][a_kq + 3][a_row] = a_reg.w;
    *(float4*)(&Bs[0][b_krow][b_cq]) = b_reg;
    __syncthreads();

    int buf = 0;
    for (int kc = 0; kc < NKCH; ++kc) {
        float4 a_n, b_n;
        if (kc + 1 < NKCH) {
            int kb = (kc + 1) * BK;
            a_n = *(const float4*)(Ag + (row0 + a_row) * KDIM + kb + a_kq);
            b_n = make_float4(0.f, 0.f, 0.f, 0.f);
            if (bvalid) b_n = *(const float4*)(Bg + (kb + b_krow) * NCOL + bcol);
        }
#pragma unroll
        for (int k = 0; k < BK; ++k) {
            float a[8], b[8];
            float4 t0 = *(const float4*)(&As[buf][k][ty * 4]);
            float4 t1 = *(const float4*)(&As[buf][k][64 + ty * 4]);
            float4 t2 = *(const float4*)(&Bs[buf][k][tx * 4]);
            float4 t3 = *(const float4*)(&Bs[buf][k][64 + tx * 4]);
            a[0] = t0.x; a[1] = t0.y; a[2] = t0.z; a[3] = t0.w;
            a[4] = t1.x; a[5] = t1.y; a[6] = t1.z; a[7] = t1.w;
            b[0] = t2.x; b[1] = t2.y; b[2] = t2.z; b[3] = t2.w;
            b[4] = t3.x; b[5] = t3.y; b[6] = t3.z; b[7] = t3.w;
#pragma unroll
            for (int i = 0; i < 8; ++i)
#pragma unroll
                for (int j = 0; j < 8; ++j)
                    acc[i][j] += a[i] * b[j];
        }
        if (kc + 1 < NKCH) {
            int nb = buf ^ 1;
            As[nb][a_kq + 0][a_row] = a_n.x;
            As[nb][a_kq + 1][a_row] = a_n.y;
            As[nb][a_kq + 2][a_row] = a_n.z;
            As[nb][a_kq + 3][a_row] = a_n.w;
            *(float4*)(&Bs[nb][b_krow][b_cq]) = b_n;
            __syncthreads();
            buf = nb;
        }
    }

    // epilogue: add bias term cnt(m) * bias2[c][w], store z
#pragma unroll
    for (int j = 0; j < 8; ++j) {
        int col = col0 + ((j < 4) ? (tx * 4 + j) : (64 + tx * 4 + (j - 4)));
        if (col >= NCOL) continue;
        int r = col % COLS_PER_N;
        int m = r / VV;
        int w = r % VV;
        float cnt = (float)((m + 1 < 9) ? (m + 1) : 9);
#pragma unroll
        for (int i = 0; i < 8; ++i) {
            int row = row0 + ((i < 4) ? (ty * 4 + i) : (64 + ty * 4 + (i - 4)));
            g_z[row * NCOL + col] = acc[i][j] + cnt * g_bias2[row * VV + w];
        }
    }
}

// ---------------------------------------------------------------------------
// LayerNorm over (c,w) per (n,m) + affine + relu + residual + relu
// block = one (n,m); thread = one channel c; 25 w-values in registers.
// ---------------------------------------------------------------------------
__global__ __launch_bounds__(256) void ln_kernel(const float* __restrict__ x,
                                                 const float* __restrict__ gamma,
                                                 const float* __restrict__ beta,
                                                 float* __restrict__ out) {
    const int nm = blockIdx.x;
    const int n = nm / LL;
    const int m = nm % LL;
    const int c = threadIdx.x;

    const float* __restrict__ zr = g_z + c * NCOL + n * COLS_PER_N + m * VV;
    float vals[25];
    float s = 0.f, s2 = 0.f;
#pragma unroll
    for (int w = 0; w < 25; ++w) {
        float v = zr[w];
        vals[w] = v;
        s += v;
        s2 += v * v;
    }

    // reduce over block (8 warps)
#pragma unroll
    for (int off = 16; off > 0; off >>= 1) {
        s  += __shfl_down_sync(0xffffffffu, s,  off);
        s2 += __shfl_down_sync(0xffffffffu, s2, off);
    }
    __shared__ float rs[8], rs2[8];
    int lane = c & 31, wid = c >> 5;
    if (lane == 0) { rs[wid] = s; rs2[wid] = s2; }
    __syncthreads();
    float tot = 0.f, tot2 = 0.f;
#pragma unroll
    for (int i = 0; i < 8; ++i) { tot += rs[i]; tot2 += rs2[i]; }

    const float inv = 1.f / 6400.f;
    float mean = tot * inv;
    float var = tot2 * inv - mean * mean;
    float rstd = rsqrtf(var + 1e-5f);

    const float* __restrict__ xr = x + (((size_t)(n * CIN + c)) * LL + m) * VV;
    float* __restrict__ orow = out + (((size_t)(n * COUT + c)) * LL + m) * VV;
#pragma unroll
    for (int w = 0; w < 25; ++w) {
        float yv = (vals[w] - mean) * rstd * gamma[c * VV + w] + beta[c * VV + w];
        yv = fmaxf(yv, 0.f);
        yv += xr[w];
        orow[w] = fmaxf(yv, 0.f);
    }
}

// ---------------------------------------------------------------------------
extern "C" void kernel_launch(void* const* d_in, const int* in_sizes, int n_in,
                              void* d_out, int out_size) {
    const float* x      = (const float*)d_in[0];
    const float* A      = (const float*)d_in[1];
    const float* conv_w = (const float*)d_in[2];
    const float* conv_b = (const float*)d_in[3];
    const float* gamma  = (const float*)d_in[4];
    const float* beta   = (const float*)d_in[5];
    const float* ei     = (const float*)d_in[6];
    float* out = (float*)d_out;

    prep_kernel<<<(COUT * KDIM + 255) / 256, 256>>>(A, conv_w, conv_b, ei);

    dim3 g0(CIN, NB);
    u_kernel<<<g0, 256>>>(x);

    dim3 g1((NCOL + BN - 1) / BN, COUT / BM);
    gemm_kernel<<<g1, 256>>>();

    ln_kernel<<<NB * LL, 256>>>(x, gamma, beta, out);
}

// round 2
// speedup vs baseline: 1.0027x; 1.0027x over previous
#include <cuda_runtime.h>

// Problem constants
#define NB   16
#define CIN  256
#define LL   300
#define VV   25
#define PP   3
#define COUT 256
#define KDIM (PP*CIN)        // 768
#define NCOL (NB*LL*VV)      // 120000
#define COLS_PER_N (LL*VV)   // 7500

// Scratch (device globals; no runtime allocation allowed)
__device__ float g_u[KDIM * NCOL];       // 768 x 120000  (~368 MB)
__device__ float g_z[COUT * NCOL];       // 256 x 120000  (~123 MB)
__device__ float g_Wall[COUT * KDIM];    // 256 x 768
__device__ float g_Aw[PP * VV * VV];
__device__ float g_bias2[COUT * VV];

// ---------------------------------------------------------------------------
// Prep: Wall[c][p*256+ci] = conv_w[(p*256+c)*256+ci];  Aw = A * edge_importance;
// bias2[c][w] = sum_p b_p[c] * sum_v Aw_p[v][w]
// ---------------------------------------------------------------------------
__global__ void prep_kernel(const float* __restrict__ A,
                            const float* __restrict__ conv_w,
                            const float* __restrict__ conv_b,
                            const float* __restrict__ ei) {
    int idx = blockIdx.x * blockDim.x + threadIdx.x;
    if (idx < COUT * KDIM) {
        int c = idx / KDIM, k = idx % KDIM;
        int p = k >> 8, ci = k & 255;
        g_Wall[idx] = conv_w[((p << 8) + c) * CIN + ci];
    }
    if (idx < PP * VV * VV) {
        g_Aw[idx] = A[idx] * ei[idx];
    }
    if (idx < COUT * VV) {
        int c = idx / VV, w = idx % VV;
        float s = 0.f;
        for (int p = 0; p < PP; ++p) {
            float b = conv_b[(p << 8) + c];
            for (int v = 0; v < VV; ++v) {
                int a = (p * VV + v) * VV + w;
                s += b * A[a] * ei[a];
            }
        }
        g_bias2[idx] = s;
    }
}

// ---------------------------------------------------------------------------
// u kernel: one block per (n, ci).
// Phase 1: sliding 9-tap window sum over l into smem xt[m][v] (padded row 28).
// Phase 2: u_p[ci][n,m,w] = sum_v xt[m][v] * Aw_p[v][w]
// ---------------------------------------------------------------------------
__global__ __launch_bounds__(256) void u_kernel(const float* __restrict__ x) {
    __shared__ __align__(16) float xt[LL * 28];
    const int n = blockIdx.y;
    const int ci = blockIdx.x;
    const float* __restrict__ xr = x + ((size_t)(n * CIN + ci)) * (LL * VV);
    const int t = threadIdx.x;

    // Phase 1: 250 threads = 25 v-lanes x 10 m-chunks of 30 frames
    if (t < 250) {
        int v = t % 25;
        int mi = t / 25;
        int m0 = mi * 30;
        float s = 0.f;
        int lstart = m0 - 8; if (lstart < 0) lstart = 0;
        for (int l = lstart; l < m0; ++l) s += xr[l * VV + v];
        for (int m = m0; m < m0 + 30; ++m) {
            s += xr[m * VV + v];
            xt[m * 28 + v] = s;
            if (m >= 8) s -= xr[(m - 8) * VV + v];
        }
    }
    __syncthreads();

    // Phase 2: warp = one m-residue class; lanes 0..24 = w
    const int w = t & 31;
    const int mg = t >> 5;   // 0..7
    if (w < 25) {
        for (int p = 0; p < PP; ++p) {
            float aw[25];
#pragma unroll
            for (int v = 0; v < 25; ++v) aw[v] = g_Aw[(p * VV + v) * VV + w];
            float* __restrict__ ubase = g_u + ((p << 8) + ci) * NCOL + n * COLS_PER_N;
            for (int m = mg; m < LL; m += 8) {
                const float4* xv4 = (const float4*)(xt + m * 28);
                float acc = 0.f;
#pragma unroll
                for (int q = 0; q < 6; ++q) {
                    float4 xv = xv4[q];
                    acc += xv.x * aw[4 * q + 0];
                    acc += xv.y * aw[4 * q + 1];
                    acc += xv.z * aw[4 * q + 2];
                    acc += xv.w * aw[4 * q + 3];
                }
                acc += xt[m * 28 + 24] * aw[24];
                ubase[m * VV + w] = acc;
            }
        }
    }
}

// ---------------------------------------------------------------------------
// GEMM: z[256 x 120000] = Wall[256 x 768] @ u[768 x 120000]  (+ bias term)
// 128x128 CTA tile, BK=8, 8x8 per-thread microtile, double-buffered smem.
// ---------------------------------------------------------------------------
#define BM 128
#define BN 128
#define BK 8
#define NKCH (KDIM / BK)   // 96

__global__ __launch_bounds__(256) void gemm_kernel() {
    __shared__ __align__(16) float As[2][BK][BM];
    __shared__ __align__(16) float Bs[2][BK][BN];

    const int tid = threadIdx.x;
    const int tx = tid % 16;
    const int ty = tid / 16;
    const int col0 = blockIdx.x * BN;
    const int row0 = blockIdx.y * BM;

    const float* __restrict__ Ag = g_Wall;
    const float* __restrict__ Bg = g_u;

    float acc[8][8];
#pragma unroll
    for (int i = 0; i < 8; ++i)
#pragma unroll
        for (int j = 0; j < 8; ++j) acc[i][j] = 0.f;

    // load mapping (one float4 per thread per tile)
    const int a_row = tid >> 1;            // 0..127
    const int a_kq  = (tid & 1) * 4;       // 0 or 4
    const int b_krow = tid >> 5;           // 0..7
    const int b_cq   = (tid & 31) * 4;     // 0..124
    const int bcol = col0 + b_cq;
    const bool bvalid = (bcol < NCOL);

    // prefetch chunk 0
    float4 a_reg = *(const float4*)(Ag + (row0 + a_row) * KDIM + a_kq);
    float4 b_reg = make_float4(0.f, 0.f, 0.f, 0.f);
    if (bvalid) b_reg = *(const float4*)(Bg + b_krow * NCOL + bcol);

    As[0][a_kq + 0][a_row] = a_reg.x;
    As[0][a_kq + 1][a_row] = a_reg.y;
    As[0][a_kq + 2][a_row] = a_reg.z;
    As[0][a_kq + 3][a_row] = a_reg.w;
    *(float4*)(&Bs[0][b_krow][b_cq]) = b_reg;
    __syncthreads();

    int buf = 0;
    for (int kc = 0; kc < NKCH; ++kc) {
        float4 a_n, b_n;
        if (kc + 1 < NKCH) {
            int kb = (kc + 1) * BK;
            a_n = *(const float4*)(Ag + (row0 + a_row) * KDIM + kb + a_kq);
            b_n = make_float4(0.f, 0.f, 0.f, 0.f);
            if (bvalid) b_n = *(const float4*)(Bg + (kb + b_krow) * NCOL + bcol);
        }
#pragma unroll
        for (int k = 0; k < BK; ++k) {
            float a[8], b[8];
            float4 t0 = *(const float4*)(&As[buf][k][ty * 4]);
            float4 t1 = *(const float4*)(&As[buf][k][64 + ty * 4]);
            float4 t2 = *(const float4*)(&Bs[buf][k][tx * 4]);
            float4 t3 = *(const float4*)(&Bs[buf][k][64 + tx * 4]);
            a[0] = t0.x; a[1] = t0.y; a[2] = t0.z; a[3] = t0.w;
            a[4] = t1.x; a[5] = t1.y; a[6] = t1.z; a[7] = t1.w;
            b[0] = t2.x; b[1] = t2.y; b[2] = t2.z; b[3] = t2.w;
            b[4] = t3.x; b[5] = t3.y; b[6] = t3.z; b[7] = t3.w;
#pragma unroll
            for (int i = 0; i < 8; ++i)
#pragma unroll
                for (int j = 0; j < 8; ++j)
                    acc[i][j] += a[i] * b[j];
        }
        if (kc + 1 < NKCH) {
            int nb = buf ^ 1;
            As[nb][a_kq + 0][a_row] = a_n.x;
            As[nb][a_kq + 1][a_row] = a_n.y;
            As[nb][a_kq + 2][a_row] = a_n.z;
            As[nb][a_kq + 3][a_row] = a_n.w;
            *(float4*)(&Bs[nb][b_krow][b_cq]) = b_n;
            __syncthreads();
            buf = nb;
        }
    }

    // epilogue: add bias term cnt(m) * bias2[c][w], store z
#pragma unroll
    for (int j = 0; j < 8; ++j) {
        int col = col0 + ((j < 4) ? (tx * 4 + j) : (64 + tx * 4 + (j - 4)));
        if (col >= NCOL) continue;
        int r = col % COLS_PER_N;
        int m = r / VV;
        int w = r % VV;
        float cnt = (float)((m + 1 < 9) ? (m + 1) : 9);
#pragma unroll
        for (int i = 0; i < 8; ++i) {
            int row = row0 + ((i < 4) ? (ty * 4 + i) : (64 + ty * 4 + (i - 4)));
            g_z[row * NCOL + col] = acc[i][j] + cnt * g_bias2[row * VV + w];
        }
    }
}

// ---------------------------------------------------------------------------
// LayerNorm over (c,w) per (n,m) + affine + relu + residual + relu
// block = one (n,m); thread = one channel c; 25 w-values in registers.
// ---------------------------------------------------------------------------
__global__ __launch_bounds__(256) void ln_kernel(const float* __restrict__ x,
                                                 const float* __restrict__ gamma,
                                                 const float* __restrict__ beta,
                                                 float* __restrict__ out) {
    const int nm = blockIdx.x;
    const int n = nm / LL;
    const int m = nm % LL;
    const int c = threadIdx.x;

    const float* __restrict__ zr = g_z + c * NCOL + n * COLS_PER_N + m * VV;
    float vals[25];
    float s = 0.f, s2 = 0.f;
#pragma unroll
    for (int w = 0; w < 25; ++w) {
        float v = zr[w];
        vals[w] = v;
        s += v;
        s2 += v * v;
    }

    // reduce over block (8 warps)
#pragma unroll
    for (int off = 16; off > 0; off >>= 1) {
        s  += __shfl_down_sync(0xffffffffu, s,  off);
        s2 += __shfl_down_sync(0xffffffffu, s2, off);
    }
    __shared__ float rs[8], rs2[8];
    int lane = c & 31, wid = c >> 5;
    if (lane == 0) { rs[wid] = s; rs2[wid] = s2; }
    __syncthreads();
    float tot = 0.f, tot2 = 0.f;
#pragma unroll
    for (int i = 0; i < 8; ++i) { tot += rs[i]; tot2 += rs2[i]; }

    const float inv = 1.f / 6400.f;
    float mean = tot * inv;
    float var = tot2 * inv - mean * mean;
    float rstd = rsqrtf(var + 1e-5f);

    const float* __restrict__ xr = x + (((size_t)(n * CIN + c)) * LL + m) * VV;
    float* __restrict__ orow = out + (((size_t)(n * COUT + c)) * LL + m) * VV;
#pragma unroll
    for (int w = 0; w < 25; ++w) {
        float yv = (vals[w] - mean) * rstd * gamma[c * VV + w] + beta[c * VV + w];
        yv = fmaxf(yv, 0.f);
        yv += xr[w];
        orow[w] = fmaxf(yv, 0.f);
    }
}

// ---------------------------------------------------------------------------
extern "C" void kernel_launch(void* const* d_in, const int* in_sizes, int n_in,
                              void* d_out, int out_size) {
    const float* x      = (const float*)d_in[0];
    const float* A      = (const float*)d_in[1];
    const float* conv_w = (const float*)d_in[2];
    const float* conv_b = (const float*)d_in[3];
    const float* gamma  = (const float*)d_in[4];
    const float* beta   = (const float*)d_in[5];
    const float* ei     = (const float*)d_in[6];
    float* out = (float*)d_out;

    prep_kernel<<<(COUT * KDIM + 255) / 256, 256>>>(A, conv_w, conv_b, ei);

    dim3 g0(CIN, NB);
    u_kernel<<<g0, 256>>>(x);

    dim3 g1((NCOL + BN - 1) / BN, COUT / BM);
    gemm_kernel<<<g1, 256>>>();

    ln_kernel<<<NB * LL, 256>>>(x, gamma, beta, out);
}

// round 4
// speedup vs baseline: 2.0703x; 2.0648x over previous
#include <cuda_runtime.h>
#include <cstdint>

#define NB 16
#define CIN 256
#define LL 300
#define VV 25
#define PP 3
#define COUT 256
#define NCOL 120000
#define CPN 7500
#define KDIM 768
#define NKC 24            // K chunks of 32

__device__ float g_u[(size_t)KDIM * NCOL];     // [k=(p,ci)][col] 368 MB
__device__ float g_zT[(size_t)NCOL * COUT];    // [col][c]        123 MB
__device__ float g_Afrag[COUT * KDIM];         // fragment-ordered Wall
__device__ float g_Aw[PP * VV * VV];
__device__ float g_bias2[COUT * VV];

__device__ __forceinline__ float to_tf32(float v) {
    uint32_t b;
    asm("cvt.rna.tf32.f32 %0, %1;" : "=r"(b) : "f"(v));
    return __uint_as_float(b);
}
__device__ __forceinline__ void cp16(uint32_t dst, const void* src, bool valid) {
    int sz = valid ? 16 : 0;
    asm volatile("cp.async.cg.shared.global [%0], [%1], 16, %2;" :: "r"(dst), "l"(src), "r"(sz));
}
__device__ __forceinline__ uint32_t smem_u32(const void* p) {
    uint32_t a;
    asm("{ .reg .u64 t; cvta.to.shared.u64 t, %1; cvt.u32.u64 %0, t; }" : "=r"(a) : "l"(p));
    return a;
}
__device__ __forceinline__ void mma_tf32(float* d, uint32_t a0, uint32_t a1, uint32_t a2,
                                         uint32_t a3, uint32_t b0, uint32_t b1) {
    asm volatile(
        "mma.sync.aligned.m16n8k8.row.col.f32.tf32.tf32.f32 "
        "{%0,%1,%2,%3}, {%4,%5,%6,%7}, {%8,%9}, {%0,%1,%2,%3};"
        : "+f"(d[0]), "+f"(d[1]), "+f"(d[2]), "+f"(d[3])
        : "r"(a0), "r"(a1), "r"(a2), "r"(a3), "r"(b0), "r"(b1));
}

// ---------------- prep: A fragments, Aw, bias2 ----------------
__global__ __launch_bounds__(256) void prep_kernel(const float* __restrict__ A,
                                                   const float* __restrict__ conv_w,
                                                   const float* __restrict__ conv_b,
                                                   const float* __restrict__ ei) {
    int e = blockIdx.x * 256 + threadIdx.x;
    if (e < COUT * KDIM) {
        int r = e / KDIM;          // output channel c
        int k = e - r * KDIM;      // (p, ci)
        int p = k >> 8, ci = k & 255;
        float w = conv_w[((p << 8) + r) * CIN + ci];
        // fragment coords
        int mtile = r >> 7, rm = r & 127, wm = rm >> 6, rmm = rm & 63;
        int fm = rmm >> 4, rr = rmm & 15;
        int kchunk = k >> 5, kk = k & 31, k8 = kk >> 3, kkk = kk & 7;
        int reg = (rr >> 3) | ((kkk >> 2) << 1);
        int lane = ((rr & 7) << 2) | (kkk & 3);
        size_t off = ((((size_t)(mtile * NKC + kchunk) * 2 + wm) * 4 + k8) * 4 + fm) * 128
                     + lane * 4 + reg;
        g_Afrag[off] = to_tf32(w);
    }
    if (e < PP * VV * VV) g_Aw[e] = A[e] * ei[e];
    if (e < COUT * VV) {
        int c = e / VV, w = e - (e / VV) * VV;
        float s = 0.f;
        for (int p = 0; p < PP; ++p) {
            float b = conv_b[(p << 8) + c];
            for (int v = 0; v < VV; ++v) {
                int a = (p * VV + v) * VV + w;
                s += b * A[a] * ei[a];
            }
        }
        g_bias2[e] = s;
    }
}

// ---------------- u kernel: window sum + graph agg (R1, verified) ----------------
__global__ __launch_bounds__(256) void u_kernel(const float* __restrict__ x) {
    __shared__ __align__(16) float xt[LL * 28];
    const int n = blockIdx.y;
    const int ci = blockIdx.x;
    const float* __restrict__ xr = x + ((size_t)(n * CIN + ci)) * CPN;
    const int t = threadIdx.x;

    if (t < 250) {
        int v = t % 25;
        int mi = t / 25;
        int m0 = mi * 30;
        float s = 0.f;
        int lstart = m0 - 8; if (lstart < 0) lstart = 0;
        for (int l = lstart; l < m0; ++l) s += xr[l * VV + v];
        for (int m = m0; m < m0 + 30; ++m) {
            s += xr[m * VV + v];
            xt[m * 28 + v] = s;
            if (m >= 8) s -= xr[(m - 8) * VV + v];
        }
    }
    __syncthreads();

    const int w = t & 31;
    const int mg = t >> 5;
    if (w < 25) {
        for (int p = 0; p < PP; ++p) {
            float aw[25];
#pragma unroll
            for (int v = 0; v < 25; ++v) aw[v] = g_Aw[(p * VV + v) * VV + w];
            float* __restrict__ ubase = g_u + (size_t)((p << 8) + ci) * NCOL + (size_t)n * CPN;
            for (int m = mg; m < LL; m += 8) {
                const float4* xv4 = (const float4*)(xt + m * 28);
                float acc = 0.f;
#pragma unroll
                for (int q = 0; q < 6; ++q) {
                    float4 xv = xv4[q];
                    acc += xv.x * aw[4 * q + 0];
                    acc += xv.y * aw[4 * q + 1];
                    acc += xv.z * aw[4 * q + 2];
                    acc += xv.w * aw[4 * q + 3];
                }
                acc += xt[m * 28 + 24] * aw[24];
                ubase[m * VV + w] = to_tf32(acc);
            }
        }
    }
}

// ---------------- tf32 mma.sync GEMM: zT[col][c] = (Wall @ u)^T ----------------
#define BM 128
#define BN 128
#define BK 32
#define BSTRIDE 136                        // floats per B smem row
#define STAGE_F (4096 + BK * BSTRIDE)      // 8448 floats per stage
#define GEMM_SMEM (2 * STAGE_F * 4)        // 67584 bytes (also fits Cs 128x132)

__global__ __launch_bounds__(256, 1) void gemm_kernel() {
    extern __shared__ float dyns[];
    const int tid = threadIdx.x;
    const int warp = tid >> 5;
    const int lane = tid & 31;
    const int wm = warp >> 2;        // 0..1
    const int wn = warp & 3;         // 0..3
    const int grp = lane >> 2;       // 0..7
    const int tig = lane & 3;        // 0..3
    const int col0 = blockIdx.x * BN;
    const int mtile = blockIdx.y;

    float acc[4][4][4];
#pragma unroll
    for (int i = 0; i < 4; ++i)
#pragma unroll
        for (int j = 0; j < 4; ++j)
#pragma unroll
            for (int r = 0; r < 4; ++r) acc[i][j][r] = 0.f;

    const uint32_t smem_base = smem_u32(dyns);

    // loader: A frag block (4096 floats) + B tile (32 rows x 128 floats)
    auto load_chunk = [&](int s, int kc) {
        uint32_t As = smem_base + (uint32_t)s * STAGE_F * 4;
        uint32_t Bs = As + 4096 * 4;
        const float* Ag = g_Afrag + (size_t)(mtile * NKC + kc) * 4096;
#pragma unroll
        for (int i = 0; i < 4; ++i) {
            int idx = i * 256 + tid;                 // 0..1023
            cp16(As + idx * 16, Ag + idx * 4, true);
            int kk = idx >> 5;
            int cq = (idx & 31) * 4;
            int col = col0 + cq;
            cp16(Bs + (kk * BSTRIDE + cq) * 4,
                 g_u + (size_t)(kc * BK + kk) * NCOL + col, col < NCOL);
        }
        asm volatile("cp.async.commit_group;" ::: "memory");
    };

    load_chunk(0, 0);
    load_chunk(1, 1);

    for (int kc = 0; kc < NKC; ++kc) {
        if (kc + 1 < NKC) asm volatile("cp.async.wait_group 1;" ::: "memory");
        else              asm volatile("cp.async.wait_group 0;" ::: "memory");
        __syncthreads();

        const int s = kc & 1;
        const float* As = dyns + s * STAGE_F;
        const float* Bs = As + 4096;

#pragma unroll
        for (int k8 = 0; k8 < 4; ++k8) {
            uint4 a[4];
#pragma unroll
            for (int fm = 0; fm < 4; ++fm)
                a[fm] = *(const uint4*)(As + wm * 2048 + k8 * 512 + fm * 128 + lane * 4);
            uint32_t b0[4], b1[4];
#pragma unroll
            for (int fn = 0; fn < 4; ++fn) {
                int nn = wn * 32 + fn * 8 + grp;
                b0[fn] = __float_as_uint(Bs[(k8 * 8 + tig) * BSTRIDE + nn]);
                b1[fn] = __float_as_uint(Bs[(k8 * 8 + tig + 4) * BSTRIDE + nn]);
            }
#pragma unroll
            for (int fm = 0; fm < 4; ++fm)
#pragma unroll
                for (int fn = 0; fn < 4; ++fn)
                    mma_tf32(acc[fm][fn], a[fm].x, a[fm].y, a[fm].z, a[fm].w, b0[fn], b1[fn]);
        }
        __syncthreads();
        if (kc + 2 < NKC) load_chunk(s, kc + 2);
    }

    // epilogue: stage C into smem as Cs[n][m] (stride 132), then coalesced zT writes
    float* Cs = dyns;
#pragma unroll
    for (int fm = 0; fm < 4; ++fm)
#pragma unroll
        for (int fn = 0; fn < 4; ++fn)
#pragma unroll
            for (int r = 0; r < 4; ++r) {
                int m = wm * 64 + fm * 16 + grp + ((r & 2) ? 8 : 0);
                int nn = wn * 32 + fn * 8 + 2 * tig + (r & 1);
                Cs[nn * 132 + m] = acc[fm][fn][r];
            }
    __syncthreads();

#pragma unroll
    for (int i = 0; i < 16; ++i) {
        int idx = i * 256 + tid;        // 0..4095
        int colr = idx >> 5;            // 0..127
        int q = (idx & 31) * 4;
        int col = col0 + colr;
        if (col < NCOL) {
            float4 v = *(const float4*)(Cs + colr * 132 + q);
            *(float4*)(g_zT + (size_t)col * COUT + mtile * 128 + q) = v;
        }
    }
}

// ---------------- fused bias + LN + relu + residual + relu ----------------
__global__ __launch_bounds__(256) void ln_kernel(const float* __restrict__ x,
                                                 const float* __restrict__ gamma,
                                                 const float* __restrict__ beta,
                                                 float* __restrict__ out) {
    __shared__ float rs[8], rs2[8];
    const int nm = blockIdx.x;
    const int n = nm / LL;
    const int m = nm - n * LL;
    const int c = threadIdx.x;

    const float cnt = (float)((m + 1 < 9) ? (m + 1) : 9);
    const float* __restrict__ zb = g_zT + (size_t)nm * VV * COUT + c;
    const float* __restrict__ b2 = g_bias2 + c * VV;

    float vals[25];
    float s = 0.f, s2 = 0.f;
#pragma unroll
    for (int w = 0; w < 25; ++w) {
        float z = zb[(size_t)w * COUT] + cnt * b2[w];
        vals[w] = z;
        s += z;
        s2 += z * z;
    }

#pragma unroll
    for (int off = 16; off > 0; off >>= 1) {
        s  += __shfl_down_sync(0xffffffffu, s,  off);
        s2 += __shfl_down_sync(0xffffffffu, s2, off);
    }
    int lane = c & 31, wrp = c >> 5;
    if (lane == 0) { rs[wrp] = s; rs2[wrp] = s2; }
    __syncthreads();
    float tot = 0.f, tot2 = 0.f;
#pragma unroll
    for (int i = 0; i < 8; ++i) { tot += rs[i]; tot2 += rs2[i]; }

    const float inv = 1.f / 6400.f;
    float mean = tot * inv;
    float var = tot2 * inv - mean * mean;
    float rstd = rsqrtf(var + 1e-5f);

    const float* __restrict__ xr = x + (((size_t)(n * CIN + c)) * LL + m) * VV;
    float* __restrict__ orow = out + (((size_t)(n * COUT + c)) * LL + m) * VV;
#pragma unroll
    for (int w = 0; w < 25; ++w) {
        float yv = (vals[w] - mean) * rstd * gamma[c * VV + w] + beta[c * VV + w];
        yv = fmaxf(yv, 0.f);
        yv += xr[w];
        orow[w] = fmaxf(yv, 0.f);
    }
}

// ---------------------------------------------------------------------------
extern "C" void kernel_launch(void* const* d_in, const int* in_sizes, int n_in,
                              void* d_out, int out_size) {
    const float* x      = (const float*)d_in[0];
    const float* A      = (const float*)d_in[1];
    const float* conv_w = (const float*)d_in[2];
    const float* conv_b = (const float*)d_in[3];
    const float* gamma  = (const float*)d_in[4];
    const float* beta   = (const float*)d_in[5];
    const float* ei     = (const float*)d_in[6];
    float* out = (float*)d_out;

    static bool attr_set = false;
    if (!attr_set) {
        cudaFuncSetAttribute(gemm_kernel, cudaFuncAttributeMaxDynamicSharedMemorySize, GEMM_SMEM);
        attr_set = true;
    }

    prep_kernel<<<(COUT * KDIM + 255) / 256, 256>>>(A, conv_w, conv_b, ei);

    dim3 gu(CIN, NB);
    u_kernel<<<gu, 256>>>(x);

    dim3 gg((NCOL + BN - 1) / BN, 2);
    gemm_kernel<<<gg, 256, GEMM_SMEM>>>();

    ln_kernel<<<NB * LL, 256>>>(x, gamma, beta, out);
}

// round 5
// speedup vs baseline: 2.1115x; 1.0199x over previous
#include <cuda_runtime.h>
#include <cstdint>

#define NB 16
#define CIN 256
#define LL 300
#define VV 25
#define PP 3
#define COUT 256
#define NCOL 120000
#define CPN 7500
#define KDIM 768
#define NKC 24            // K chunks of 32

__device__ float g_u[(size_t)KDIM * NCOL];     // [k=(p,ci)][col] 368 MB
__device__ float g_zT[(size_t)NCOL * COUT];    // [col][c] (biased) 123 MB
__device__ float g_Afrag[COUT * KDIM];         // fragment-ordered Wall
__device__ float g_Aw[PP * VV * VV];
__device__ float g_bias2[COUT * VV];
__device__ float g_sum[NB * LL];
__device__ float g_sum2[NB * LL];

__device__ __forceinline__ float to_tf32(float v) {
    uint32_t b;
    asm("cvt.rna.tf32.f32 %0, %1;" : "=r"(b) : "f"(v));
    return __uint_as_float(b);
}
__device__ __forceinline__ void cp16(uint32_t dst, const void* src, bool valid) {
    int sz = valid ? 16 : 0;
    asm volatile("cp.async.cg.shared.global [%0], [%1], 16, %2;" :: "r"(dst), "l"(src), "r"(sz));
}
__device__ __forceinline__ uint32_t smem_u32(const void* p) {
    uint32_t a;
    asm("{ .reg .u64 t; cvta.to.shared.u64 t, %1; cvt.u32.u64 %0, t; }" : "=r"(a) : "l"(p));
    return a;
}
__device__ __forceinline__ void mma_tf32(float* d, uint32_t a0, uint32_t a1, uint32_t a2,
                                         uint32_t a3, uint32_t b0, uint32_t b1) {
    asm volatile(
        "mma.sync.aligned.m16n8k8.row.col.f32.tf32.tf32.f32 "
        "{%0,%1,%2,%3}, {%4,%5,%6,%7}, {%8,%9}, {%0,%1,%2,%3};"
        : "+f"(d[0]), "+f"(d[1]), "+f"(d[2]), "+f"(d[3])
        : "r"(a0), "r"(a1), "r"(a2), "r"(a3), "r"(b0), "r"(b1));
}

// ---------------- prep: A fragments, Aw, bias2, zero stats ----------------
__global__ __launch_bounds__(256) void prep_kernel(const float* __restrict__ A,
                                                   const float* __restrict__ conv_w,
                                                   const float* __restrict__ conv_b,
                                                   const float* __restrict__ ei) {
    int e = blockIdx.x * 256 + threadIdx.x;
    if (e < COUT * KDIM) {
        int r = e / KDIM;
        int k = e - r * KDIM;
        int p = k >> 8, ci = k & 255;
        float w = conv_w[((p << 8) + r) * CIN + ci];
        int mtile = r >> 7, rm = r & 127, wm = rm >> 6, rmm = rm & 63;
        int fm = rmm >> 4, rr = rmm & 15;
        int kchunk = k >> 5, kk = k & 31, k8 = kk >> 3, kkk = kk & 7;
        int reg = (rr >> 3) | ((kkk >> 2) << 1);
        int lane = ((rr & 7) << 2) | (kkk & 3);
        size_t off = ((((size_t)(mtile * NKC + kchunk) * 2 + wm) * 4 + k8) * 4 + fm) * 128
                     + lane * 4 + reg;
        g_Afrag[off] = to_tf32(w);
    }
    if (e < PP * VV * VV) g_Aw[e] = A[e] * ei[e];
    if (e < COUT * VV) {
        int c = e / VV, w = e - (e / VV) * VV;
        float s = 0.f;
        for (int p = 0; p < PP; ++p) {
            float b = conv_b[(p << 8) + c];
            for (int v = 0; v < VV; ++v) {
                int a = (p * VV + v) * VV + w;
                s += b * A[a] * ei[a];
            }
        }
        g_bias2[e] = s;
    }
    if (e < NB * LL) { g_sum[e] = 0.f; g_sum2[e] = 0.f; }
}

// ---------------- u kernel: window sum + graph agg, smem-staged stores ----------------
__global__ __launch_bounds__(256) void u_kernel(const float* __restrict__ x) {
    extern __shared__ __align__(16) float us[];
    float* xt = us;            // 300 * 28
    float* ut = us + LL * 28;  // 7500
    const int n = blockIdx.y;
    const int ci = blockIdx.x;
    const float* __restrict__ xr = x + ((size_t)(n * CIN + ci)) * CPN;
    const int t = threadIdx.x;

    if (t < 250) {
        int v = t % 25;
        int mi = t / 25;
        int m0 = mi * 30;
        float s = 0.f;
        int lstart = m0 - 8; if (lstart < 0) lstart = 0;
        for (int l = lstart; l < m0; ++l) s += xr[l * VV + v];
        for (int m = m0; m < m0 + 30; ++m) {
            s += xr[m * VV + v];
            xt[m * 28 + v] = s;
            if (m >= 8) s -= xr[(m - 8) * VV + v];
        }
    }
    __syncthreads();

    const int w = t & 31;
    const int mg = t >> 5;
    float aw[25];
    for (int p = 0; p < PP; ++p) {
        if (w < 25) {
#pragma unroll
            for (int v = 0; v < 25; ++v) aw[v] = g_Aw[(p * VV + v) * VV + w];
            for (int m = mg; m < LL; m += 8) {
                const float4* xv4 = (const float4*)(xt + m * 28);
                float acc = 0.f;
#pragma unroll
                for (int q = 0; q < 6; ++q) {
                    float4 xv = xv4[q];
                    acc += xv.x * aw[4 * q + 0];
                    acc += xv.y * aw[4 * q + 1];
                    acc += xv.z * aw[4 * q + 2];
                    acc += xv.w * aw[4 * q + 3];
                }
                acc += xt[m * 28 + 24] * aw[24];
                ut[m * VV + w] = to_tf32(acc);
            }
        }
        __syncthreads();
        float4* __restrict__ dst = (float4*)(g_u + (size_t)((p << 8) + ci) * NCOL + (size_t)n * CPN);
        const float4* srcv = (const float4*)ut;
        for (int i = t; i < CPN / 4; i += 256) dst[i] = srcv[i];
        __syncthreads();
    }
}

// ---------------- tf32 mma.sync GEMM + bias + LN-stats epilogue ----------------
#define BM 128
#define BN 128
#define BK 32
#define BSTRIDE 136
#define STAGE_F (4096 + BK * BSTRIDE)
#define GEMM_SMEM (2 * STAGE_F * 4)

__global__ __launch_bounds__(256, 1) void gemm_kernel() {
    extern __shared__ float dyns[];
    const int tid = threadIdx.x;
    const int warp = tid >> 5;
    const int lane = tid & 31;
    const int wm = warp >> 2;
    const int wn = warp & 3;
    const int grp = lane >> 2;
    const int tig = lane & 3;
    const int col0 = blockIdx.x * BN;
    const int mtile = blockIdx.y;

    float acc[4][4][4];
#pragma unroll
    for (int i = 0; i < 4; ++i)
#pragma unroll
        for (int j = 0; j < 4; ++j)
#pragma unroll
            for (int r = 0; r < 4; ++r) acc[i][j][r] = 0.f;

    const uint32_t smem_base = smem_u32(dyns);

    auto load_chunk = [&](int s, int kc) {
        uint32_t As = smem_base + (uint32_t)s * STAGE_F * 4;
        uint32_t Bs = As + 4096 * 4;
        const float* Ag = g_Afrag + (size_t)(mtile * NKC + kc) * 4096;
#pragma unroll
        for (int i = 0; i < 4; ++i) {
            int idx = i * 256 + tid;
            cp16(As + idx * 16, Ag + idx * 4, true);
            int kk = idx >> 5;
            int cq = (idx & 31) * 4;
            int col = col0 + cq;
            cp16(Bs + (kk * BSTRIDE + cq) * 4,
                 g_u + (size_t)(kc * BK + kk) * NCOL + col, col < NCOL);
        }
        asm volatile("cp.async.commit_group;" ::: "memory");
    };

    load_chunk(0, 0);
    load_chunk(1, 1);

    for (int kc = 0; kc < NKC; ++kc) {
        if (kc + 1 < NKC) asm volatile("cp.async.wait_group 1;" ::: "memory");
        else              asm volatile("cp.async.wait_group 0;" ::: "memory");
        __syncthreads();

        const int s = kc & 1;
        const float* As = dyns + s * STAGE_F;
        const float* Bs = As + 4096;

#pragma unroll
        for (int k8 = 0; k8 < 4; ++k8) {
            uint4 a[4];
#pragma unroll
            for (int fm = 0; fm < 4; ++fm)
                a[fm] = *(const uint4*)(As + wm * 2048 + k8 * 512 + fm * 128 + lane * 4);
            uint32_t b0[4], b1[4];
#pragma unroll
            for (int fn = 0; fn < 4; ++fn) {
                int nn = wn * 32 + fn * 8 + grp;
                b0[fn] = __float_as_uint(Bs[(k8 * 8 + tig) * BSTRIDE + nn]);
                b1[fn] = __float_as_uint(Bs[(k8 * 8 + tig + 4) * BSTRIDE + nn]);
            }
#pragma unroll
            for (int fm = 0; fm < 4; ++fm)
#pragma unroll
                for (int fn = 0; fn < 4; ++fn)
                    mma_tf32(acc[fm][fn], a[fm].x, a[fm].y, a[fm].z, a[fm].w, b0[fn], b1[fn]);
        }
        __syncthreads();
        if (kc + 2 < NKC) load_chunk(s, kc + 2);
    }

    // stage C as Cs[col][c] (stride 132)
    float* Cs = dyns;
#pragma unroll
    for (int fm = 0; fm < 4; ++fm)
#pragma unroll
        for (int fn = 0; fn < 4; ++fn)
#pragma unroll
            for (int r = 0; r < 4; ++r) {
                int m = wm * 64 + fm * 16 + grp + ((r & 2) ? 8 : 0);
                int nn = wn * 32 + fn * 8 + 2 * tig + (r & 1);
                Cs[nn * 132 + m] = acc[fm][fn][r];
            }
    __syncthreads();

    // bias add + coalesced zT store + warp-reduced LN stats atomics
#pragma unroll
    for (int i = 0; i < 16; ++i) {
        int idx = i * 256 + tid;
        int colr = idx >> 5;             // uniform per warp
        int q = (idx & 31) * 4;
        int col = col0 + colr;
        if (col < NCOL) {
            float4 v = *(const float4*)(Cs + colr * 132 + q);
            int rm = col % CPN;
            int m = rm / VV;
            int w = rm - m * VV;
            float cnt = (float)((m + 1 < 9) ? (m + 1) : 9);
            int cbase = mtile * 128 + q;
            v.x += cnt * g_bias2[(cbase + 0) * VV + w];
            v.y += cnt * g_bias2[(cbase + 1) * VV + w];
            v.z += cnt * g_bias2[(cbase + 2) * VV + w];
            v.w += cnt * g_bias2[(cbase + 3) * VV + w];
            *(float4*)(g_zT + (size_t)col * COUT + cbase) = v;

            float s = v.x + v.y + v.z + v.w;
            float s2 = v.x * v.x + v.y * v.y + v.z * v.z + v.w * v.w;
#pragma unroll
            for (int off = 16; off > 0; off >>= 1) {
                s  += __shfl_down_sync(0xffffffffu, s,  off);
                s2 += __shfl_down_sync(0xffffffffu, s2, off);
            }
            if ((tid & 31) == 0) {
                int nm = col / VV;
                atomicAdd(&g_sum[nm], s);
                atomicAdd(&g_sum2[nm], s2);
            }
        }
    }
}

// ---------------- apply: LN + relu + residual + relu, transpose-coalesced ----------------
__global__ __launch_bounds__(256) void apply_kernel(const float* __restrict__ x,
                                                    const float* __restrict__ gamma,
                                                    const float* __restrict__ beta,
                                                    float* __restrict__ out) {
    __shared__ float tile[32][33];
    const int n = blockIdx.z;
    const int cc0 = blockIdx.y * 32;
    const int col0 = blockIdx.x * 32;
    const int tx = threadIdx.x;   // 0..31
    const int ty = threadIdx.y;   // 0..7

    // load zT coalesced on c
#pragma unroll
    for (int k = 0; k < 4; ++k) {
        int colr = col0 + ty + k * 8;
        if (colr < CPN)
            tile[ty + k * 8][tx] = g_zT[((size_t)(n * CPN + colr)) * COUT + cc0 + tx];
    }
    __syncthreads();

    const int col = col0 + tx;
    if (col >= CPN) return;
    const int m = col / VV;
    const int w = col - m * VV;
    const int nm = n * LL + m;

    const float inv = 1.f / 6400.f;
    float mean = g_sum[nm] * inv;
    float var = g_sum2[nm] * inv - mean * mean;
    float rstd = rsqrtf(var + 1e-5f);

#pragma unroll
    for (int k = 0; k < 4; ++k) {
        int c = cc0 + ty + k * 8;
        float z = tile[tx][ty + k * 8];
        float yv = (z - mean) * rstd * gamma[c * VV + w] + beta[c * VV + w];
        yv = fmaxf(yv, 0.f);
        size_t gidx = ((size_t)(n * CIN + c)) * CPN + col;
        yv += x[gidx];
        out[gidx] = fmaxf(yv, 0.f);
    }
}

// ---------------------------------------------------------------------------
extern "C" void kernel_launch(void* const* d_in, const int* in_sizes, int n_in,
                              void* d_out, int out_size) {
    const float* x      = (const float*)d_in[0];
    const float* A      = (const float*)d_in[1];
    const float* conv_w = (const float*)d_in[2];
    const float* conv_b = (const float*)d_in[3];
    const float* gamma  = (const float*)d_in[4];
    const float* beta   = (const float*)d_in[5];
    const float* ei     = (const float*)d_in[6];
    float* out = (float*)d_out;

    const int USMEM = (LL * 28 + CPN) * 4;   // 63600 bytes
    cudaFuncSetAttribute(gemm_kernel, cudaFuncAttributeMaxDynamicSharedMemorySize, GEMM_SMEM);
    cudaFuncSetAttribute(u_kernel, cudaFuncAttributeMaxDynamicSharedMemorySize, USMEM);

    prep_kernel<<<(COUT * KDIM + 255) / 256, 256>>>(A, conv_w, conv_b, ei);

    dim3 gu(CIN, NB);
    u_kernel<<<gu, 256, USMEM>>>(x);

    dim3 gg((NCOL + BN - 1) / BN, 2);
    gemm_kernel<<<gg, 256, GEMM_SMEM>>>();

    dim3 ga((CPN + 31) / 32, COUT / 32, NB);
    apply_kernel<<<ga, dim3(32, 8)>>>(x, gamma, beta, out);
}

// round 6
// speedup vs baseline: 2.4764x; 1.1728x over previous
#include <cuda_runtime.h>
#include <cuda_fp16.h>
#include <cstdint>

#define NB 16
#define CIN 256
#define LL 300
#define VV 25
#define PP 3
#define COUT 256
#define NCOL 120000
#define CPN 7500
#define KDIM 768
#define NKC 24            // K chunks of 32

__device__ __half g_uh[(size_t)KDIM * NCOL];    // [k=(p,ci)][col] 184 MB
__device__ float g_zT[(size_t)NCOL * COUT];     // [col][c] (biased) 123 MB
__device__ __half g_Afrag[COUT * KDIM];         // fp16 fragment-ordered Wall
__device__ float g_Aw[PP * VV * VV];
__device__ float g_bias2[COUT * VV];
__device__ float g_sum[NB * LL];
__device__ float g_sum2[NB * LL];

__device__ __forceinline__ void cp16(uint32_t dst, const void* src, bool valid) {
    int sz = valid ? 16 : 0;
    asm volatile("cp.async.cg.shared.global [%0], [%1], 16, %2;" :: "r"(dst), "l"(src), "r"(sz));
}
__device__ __forceinline__ uint32_t smem_u32(const void* p) {
    uint32_t a;
    asm("{ .reg .u64 t; cvta.to.shared.u64 t, %1; cvt.u32.u64 %0, t; }" : "=r"(a) : "l"(p));
    return a;
}
__device__ __forceinline__ void mma_f16(float* d, uint32_t a0, uint32_t a1, uint32_t a2,
                                        uint32_t a3, uint32_t b0, uint32_t b1) {
    asm volatile(
        "mma.sync.aligned.m16n8k16.row.col.f32.f16.f16.f32 "
        "{%0,%1,%2,%3}, {%4,%5,%6,%7}, {%8,%9}, {%0,%1,%2,%3};"
        : "+f"(d[0]), "+f"(d[1]), "+f"(d[2]), "+f"(d[3])
        : "r"(a0), "r"(a1), "r"(a2), "r"(a3), "r"(b0), "r"(b1));
}

// ---------------- prep: fp16 A fragments (m16n8k16 order), Aw, bias2, zero stats ----
__global__ __launch_bounds__(256) void prep_kernel(const float* __restrict__ A,
                                                   const float* __restrict__ conv_w,
                                                   const float* __restrict__ conv_b,
                                                   const float* __restrict__ ei) {
    int e = blockIdx.x * 256 + threadIdx.x;
    if (e < COUT * KDIM) {
        int r = e / KDIM;
        int k = e - r * KDIM;
        int p = k >> 8, ci = k & 255;
        float w = conv_w[((p << 8) + r) * CIN + ci];
        int mtile = r >> 7, rm = r & 127, wm = rm >> 6, rmm = rm & 63;
        int fm = rmm >> 4, rr = rmm & 15;
        int kchunk = k >> 5, kk = k & 31, k16 = kk >> 4, kkk = kk & 15;
        int reg = (rr >> 3) | ((kkk >> 3) << 1);
        int lane = ((rr & 7) << 2) | ((kkk & 7) >> 1);
        int hl = kkk & 1;
        size_t off = ((((size_t)(mtile * NKC + kchunk) * 2 + wm) * 2 + k16) * 4 + fm) * 256
                     + lane * 8 + reg * 2 + hl;
        g_Afrag[off] = __float2half_rn(w);
    }
    if (e < PP * VV * VV) g_Aw[e] = A[e] * ei[e];
    if (e < COUT * VV) {
        int c = e / VV, w = e - (e / VV) * VV;
        float s = 0.f;
        for (int p = 0; p < PP; ++p) {
            float b = conv_b[(p << 8) + c];
            for (int v = 0; v < VV; ++v) {
                int a = (p * VV + v) * VV + w;
                s += b * A[a] * ei[a];
            }
        }
        g_bias2[e] = s;
    }
    if (e < NB * LL) { g_sum[e] = 0.f; g_sum2[e] = 0.f; }
}

// ---------------- u kernel: window sum + graph agg, fp16 smem-staged stores --------
__global__ __launch_bounds__(256) void u_kernel(const float* __restrict__ x) {
    extern __shared__ __align__(16) float us[];
    float* xt = us;                           // 300 * 28 floats
    __half* ut = (__half*)(us + LL * 28);     // 7500 halves
    const int n = blockIdx.y;
    const int ci = blockIdx.x;
    const float* __restrict__ xr = x + ((size_t)(n * CIN + ci)) * CPN;
    const int t = threadIdx.x;

    if (t < 250) {
        int v = t % 25;
        int mi = t / 25;
        int m0 = mi * 30;
        float s = 0.f;
        int lstart = m0 - 8; if (lstart < 0) lstart = 0;
        for (int l = lstart; l < m0; ++l) s += xr[l * VV + v];
        for (int m = m0; m < m0 + 30; ++m) {
            s += xr[m * VV + v];
            xt[m * 28 + v] = s;
            if (m >= 8) s -= xr[(m - 8) * VV + v];
        }
    }
    __syncthreads();

    const int w = t & 31;
    const int mg = t >> 5;
    float aw[25];
    for (int p = 0; p < PP; ++p) {
        if (w < 25) {
#pragma unroll
            for (int v = 0; v < 25; ++v) aw[v] = g_Aw[(p * VV + v) * VV + w];
            for (int m = mg; m < LL; m += 8) {
                const float4* xv4 = (const float4*)(xt + m * 28);
                float acc = 0.f;
#pragma unroll
                for (int q = 0; q < 6; ++q) {
                    float4 xv = xv4[q];
                    acc += xv.x * aw[4 * q + 0];
                    acc += xv.y * aw[4 * q + 1];
                    acc += xv.z * aw[4 * q + 2];
                    acc += xv.w * aw[4 * q + 3];
                }
                acc += xt[m * 28 + 24] * aw[24];
                ut[m * VV + w] = __float2half_rn(acc);
            }
        }
        __syncthreads();
        uint32_t* __restrict__ dst =
            (uint32_t*)(g_uh + (size_t)((p << 8) + ci) * NCOL + (size_t)n * CPN);
        const uint32_t* srcv = (const uint32_t*)ut;
        for (int i = t; i < CPN / 2; i += 256) dst[i] = srcv[i];
        __syncthreads();
    }
}

// ---------------- fp16 mma.sync GEMM + bias + LN-stats epilogue ----------------
#define BN 128
#define BK 32
#define BSH 136                                    // halves per B smem row
#define STAGE_H (4096 + BK * BSH)                  // 8448 halves per stage
#define GEMM_SMEM 67584                            // Cs 128x132 floats dominates

__global__ __launch_bounds__(256, 1) void gemm_kernel() {
    extern __shared__ float dyns[];
    __half* sh = (__half*)dyns;
    const int tid = threadIdx.x;
    const int warp = tid >> 5;
    const int lane = tid & 31;
    const int wm = warp >> 2;
    const int wn = warp & 3;
    const int grp = lane >> 2;
    const int tig = lane & 3;
    const int col0 = blockIdx.x * BN;
    const int mtile = blockIdx.y;

    float acc[4][4][4];
#pragma unroll
    for (int i = 0; i < 4; ++i)
#pragma unroll
        for (int j = 0; j < 4; ++j)
#pragma unroll
            for (int r = 0; r < 4; ++r) acc[i][j][r] = 0.f;

    const uint32_t smem_base = smem_u32(dyns);

    auto load_chunk = [&](int s, int kc) {
        uint32_t As_b = smem_base + (uint32_t)s * STAGE_H * 2;
        uint32_t Bs_b = As_b + 4096 * 2;
        const __half* Ag = g_Afrag + (size_t)(mtile * NKC + kc) * 4096;
#pragma unroll
        for (int i = 0; i < 2; ++i) {
            int idx = i * 256 + tid;               // 0..511: A fragments
            cp16(As_b + idx * 16, Ag + idx * 8, true);
        }
#pragma unroll
        for (int i = 0; i < 2; ++i) {
            int j = i * 256 + tid;                 // 0..511: B tile
            int kk = j >> 4;                       // 0..31
            int cq = (j & 15) * 8;                 // 0..120
            int col = col0 + cq;
            cp16(Bs_b + (kk * BSH + cq) * 2,
                 g_uh + (size_t)(kc * BK + kk) * NCOL + col, col < NCOL);
        }
        asm volatile("cp.async.commit_group;" ::: "memory");
    };

    load_chunk(0, 0);
    load_chunk(1, 1);

    for (int kc = 0; kc < NKC; ++kc) {
        if (kc + 1 < NKC) asm volatile("cp.async.wait_group 1;" ::: "memory");
        else              asm volatile("cp.async.wait_group 0;" ::: "memory");
        __syncthreads();

        const int s = kc & 1;
        const __half* As = sh + s * STAGE_H;
        const __half* Bs = As + 4096;

#pragma unroll
        for (int k16 = 0; k16 < 2; ++k16) {
            uint4 a[4];
#pragma unroll
            for (int fm = 0; fm < 4; ++fm)
                a[fm] = *(const uint4*)(As + (((wm * 2 + k16) * 4 + fm) << 8) + lane * 8);
            uint32_t b0[4], b1[4];
#pragma unroll
            for (int fn = 0; fn < 4; ++fn) {
                int nn = wn * 32 + fn * 8 + grp;
                const __half* bp = Bs + (k16 * 16 + 2 * tig) * BSH + nn;
                uint32_t lo0 = *(const unsigned short*)bp;
                uint32_t hi0 = *(const unsigned short*)(bp + BSH);
                b0[fn] = lo0 | (hi0 << 16);
                uint32_t lo1 = *(const unsigned short*)(bp + 8 * BSH);
                uint32_t hi1 = *(const unsigned short*)(bp + 9 * BSH);
                b1[fn] = lo1 | (hi1 << 16);
            }
#pragma unroll
            for (int fm = 0; fm < 4; ++fm)
#pragma unroll
                for (int fn = 0; fn < 4; ++fn)
                    mma_f16(acc[fm][fn], a[fm].x, a[fm].y, a[fm].z, a[fm].w, b0[fn], b1[fn]);
        }
        __syncthreads();
        if (kc + 2 < NKC) load_chunk(s, kc + 2);
    }

    // stage C as Cs[col][c] (stride 132)
    float* Cs = dyns;
#pragma unroll
    for (int fm = 0; fm < 4; ++fm)
#pragma unroll
        for (int fn = 0; fn < 4; ++fn)
#pragma unroll
            for (int r = 0; r < 4; ++r) {
                int m = wm * 64 + fm * 16 + grp + ((r & 2) ? 8 : 0);
                int nn = wn * 32 + fn * 8 + 2 * tig + (r & 1);
                Cs[nn * 132 + m] = acc[fm][fn][r];
            }
    __syncthreads();

    // bias add + coalesced zT store + warp-reduced LN stats atomics
#pragma unroll
    for (int i = 0; i < 16; ++i) {
        int idx = i * 256 + tid;
        int colr = idx >> 5;
        int q = (idx & 31) * 4;
        int col = col0 + colr;
        if (col < NCOL) {
            float4 v = *(const float4*)(Cs + colr * 132 + q);
            int rm = col % CPN;
            int m = rm / VV;
            int w = rm - m * VV;
            float cnt = (float)((m + 1 < 9) ? (m + 1) : 9);
            int cbase = mtile * 128 + q;
            v.x += cnt * g_bias2[(cbase + 0) * VV + w];
            v.y += cnt * g_bias2[(cbase + 1) * VV + w];
            v.z += cnt * g_bias2[(cbase + 2) * VV + w];
            v.w += cnt * g_bias2[(cbase + 3) * VV + w];
            *(float4*)(g_zT + (size_t)col * COUT + cbase) = v;

            float s = v.x + v.y + v.z + v.w;
            float s2 = v.x * v.x + v.y * v.y + v.z * v.z + v.w * v.w;
#pragma unroll
            for (int off = 16; off > 0; off >>= 1) {
                s  += __shfl_down_sync(0xffffffffu, s,  off);
                s2 += __shfl_down_sync(0xffffffffu, s2, off);
            }
            if ((tid & 31) == 0) {
                int nm = col / VV;
                atomicAdd(&g_sum[nm], s);
                atomicAdd(&g_sum2[nm], s2);
            }
        }
    }
}

// ---------------- apply: LN + relu + residual + relu, transpose-coalesced ----------
__global__ __launch_bounds__(256) void apply_kernel(const float* __restrict__ x,
                                                    const float* __restrict__ gamma,
                                                    const float* __restrict__ beta,
                                                    float* __restrict__ out) {
    __shared__ float tile[32][33];
    const int n = blockIdx.z;
    const int cc0 = blockIdx.y * 32;
    const int col0 = blockIdx.x * 32;
    const int tx = threadIdx.x;
    const int ty = threadIdx.y;

#pragma unroll
    for (int k = 0; k < 4; ++k) {
        int colr = col0 + ty + k * 8;
        if (colr < CPN)
            tile[ty + k * 8][tx] = g_zT[((size_t)(n * CPN + colr)) * COUT + cc0 + tx];
    }
    __syncthreads();

    const int col = col0 + tx;
    if (col >= CPN) return;
    const int m = col / VV;
    const int w = col - m * VV;
    const int nm = n * LL + m;

    const float inv = 1.f / 6400.f;
    float mean = g_sum[nm] * inv;
    float var = g_sum2[nm] * inv - mean * mean;
    float rstd = rsqrtf(var + 1e-5f);

#pragma unroll
    for (int k = 0; k < 4; ++k) {
        int c = cc0 + ty + k * 8;
        float z = tile[tx][ty + k * 8];
        float yv = (z - mean) * rstd * gamma[c * VV + w] + beta[c * VV + w];
        yv = fmaxf(yv, 0.f);
        size_t gidx = ((size_t)(n * CIN + c)) * CPN + col;
        yv += x[gidx];
        out[gidx] = fmaxf(yv, 0.f);
    }
}

// ---------------------------------------------------------------------------
extern "C" void kernel_launch(void* const* d_in, const int* in_sizes, int n_in,
                              void* d_out, int out_size) {
    const float* x      = (const float*)d_in[0];
    const float* A      = (const float*)d_in[1];
    const float* conv_w = (const float*)d_in[2];
    const float* conv_b = (const float*)d_in[3];
    const float* gamma  = (const float*)d_in[4];
    const float* beta   = (const float*)d_in[5];
    const float* ei     = (const float*)d_in[6];
    float* out = (float*)d_out;

    const int USMEM = LL * 28 * 4 + CPN * 2;   // 48600 bytes
    cudaFuncSetAttribute(gemm_kernel, cudaFuncAttributeMaxDynamicSharedMemorySize, GEMM_SMEM);
    cudaFuncSetAttribute(u_kernel, cudaFuncAttributeMaxDynamicSharedMemorySize, USMEM);

    prep_kernel<<<(COUT * KDIM + 255) / 256, 256>>>(A, conv_w, conv_b, ei);

    dim3 gu(CIN, NB);
    u_kernel<<<gu, 256, USMEM>>>(x);

    dim3 gg((NCOL + BN - 1) / BN, 2);
    gemm_kernel<<<gg, 256, GEMM_SMEM>>>();

    dim3 ga((CPN + 31) / 32, COUT / 32, NB);
    apply_kernel<<<ga, dim3(32, 8)>>>(x, gamma, beta, out);
}

// round 7
// speedup vs baseline: 2.5233x; 1.0189x over previous
#include <cuda_runtime.h>
#include <cuda_fp16.h>
#include <cstdint>

#define NB 16
#define CIN 256
#define LL 300
#define VV 25
#define PP 3
#define COUT 256
#define NCOL 120000
#define CPN 7500
#define KDIM 768
#define NKC 24            // K chunks of 32

#define BN 100            // 4 LN-frame groups per CTA
#define NPAD 104          // padded to n8 multiple
#define BSHB 112          // halves per B smem row
#define ASTG 8192         // A halves per chunk
#define STAGE_B (ASTG * 2 + 32 * BSHB * 2)      // 23552 bytes per stage
#define CS_STRIDE 261
#define GEMM_SMEM (BN * CS_STRIDE * 4 > 2 * STAGE_B ? BN * CS_STRIDE * 4 : 2 * STAGE_B)

__device__ __half g_uh[(size_t)KDIM * NCOL];    // [k=(p,ci)][col] 184 MB
__device__ __half g_Afrag[COUT * KDIM];         // fp16 fragment-ordered Wall
__device__ float g_Aw[PP * VV * VV];
__device__ float g_bias2[COUT * VV];

__device__ __forceinline__ void cp16(uint32_t dst, const void* src) {
    asm volatile("cp.async.cg.shared.global [%0], [%1], 16;" :: "r"(dst), "l"(src));
}
__device__ __forceinline__ void cp8(uint32_t dst, const void* src) {
    asm volatile("cp.async.ca.shared.global [%0], [%1], 8;" :: "r"(dst), "l"(src));
}
__device__ __forceinline__ uint32_t smem_u32(const void* p) {
    uint32_t a;
    asm("{ .reg .u64 t; cvta.to.shared.u64 t, %1; cvt.u32.u64 %0, t; }" : "=r"(a) : "l"(p));
    return a;
}
__device__ __forceinline__ void mma_f16(float* d, uint32_t a0, uint32_t a1, uint32_t a2,
                                        uint32_t a3, uint32_t b0, uint32_t b1) {
    asm volatile(
        "mma.sync.aligned.m16n8k16.row.col.f32.f16.f16.f32 "
        "{%0,%1,%2,%3}, {%4,%5,%6,%7}, {%8,%9}, {%0,%1,%2,%3};"
        : "+f"(d[0]), "+f"(d[1]), "+f"(d[2]), "+f"(d[3])
        : "r"(a0), "r"(a1), "r"(a2), "r"(a3), "r"(b0), "r"(b1));
}

// ---------------- prep: fp16 A fragments (M256 x 8-warp tiling), Aw, bias2 ---------
__global__ __launch_bounds__(256) void prep_kernel(const float* __restrict__ A,
                                                   const float* __restrict__ conv_w,
                                                   const float* __restrict__ conv_b,
                                                   const float* __restrict__ ei) {
    int e = blockIdx.x * 256 + threadIdx.x;
    if (e < COUT * KDIM) {
        int r = e / KDIM;          // output channel c (0..255)
        int k = e - r * KDIM;      // (p, ci)
        int p = k >> 8, ci = k & 255;
        float w = conv_w[((p << 8) + r) * CIN + ci];
        int wm = r >> 5, fm = (r >> 4) & 1, rr = r & 15;
        int kchunk = k >> 5, k16 = (k >> 4) & 1, kkk = k & 15;
        int reg = (rr >> 3) | ((kkk >> 3) << 1);
        int lane = ((rr & 7) << 2) | ((kkk & 7) >> 1);
        int hl = kkk & 1;
        size_t off = ((((size_t)(kchunk * 8 + wm) * 2 + k16) * 2 + fm) * 256)
                     + lane * 8 + reg * 2 + hl;
        g_Afrag[off] = __float2half_rn(w);
    }
    if (e < PP * VV * VV) g_Aw[e] = A[e] * ei[e];
    if (e < COUT * VV) {
        int c = e / VV, w = e - (e / VV) * VV;
        float s = 0.f;
        for (int p = 0; p < PP; ++p) {
            float b = conv_b[(p << 8) + c];
            for (int v = 0; v < VV; ++v) {
                int a = (p * VV + v) * VV + w;
                s += b * A[a] * ei[a];
            }
        }
        g_bias2[e] = s;
    }
}

// ---------------- u kernel: window sum + graph agg, fp16 smem-staged stores --------
__global__ __launch_bounds__(256) void u_kernel(const float* __restrict__ x) {
    extern __shared__ __align__(16) float us[];
    float* xt = us;                           // 300 * 28 floats
    __half* ut = (__half*)(us + LL * 28);     // 7500 halves
    const int n = blockIdx.y;
    const int ci = blockIdx.x;
    const float* __restrict__ xr = x + ((size_t)(n * CIN + ci)) * CPN;
    const int t = threadIdx.x;

    if (t < 250) {
        int v = t % 25;
        int mi = t / 25;
        int m0 = mi * 30;
        float s = 0.f;
        int lstart = m0 - 8; if (lstart < 0) lstart = 0;
        for (int l = lstart; l < m0; ++l) s += xr[l * VV + v];
        for (int m = m0; m < m0 + 30; ++m) {
            s += xr[m * VV + v];
            xt[m * 28 + v] = s;
            if (m >= 8) s -= xr[(m - 8) * VV + v];
        }
    }
    __syncthreads();

    const int w = t & 31;
    const int mg = t >> 5;
    float aw[25];
    for (int p = 0; p < PP; ++p) {
        if (w < 25) {
#pragma unroll
            for (int v = 0; v < 25; ++v) aw[v] = g_Aw[(p * VV + v) * VV + w];
            for (int m = mg; m < LL; m += 8) {
                const float4* xv4 = (const float4*)(xt + m * 28);
                float acc = 0.f;
#pragma unroll
                for (int q = 0; q < 6; ++q) {
                    float4 xv = xv4[q];
                    acc += xv.x * aw[4 * q + 0];
                    acc += xv.y * aw[4 * q + 1];
                    acc += xv.z * aw[4 * q + 2];
                    acc += xv.w * aw[4 * q + 3];
                }
                acc += xt[m * 28 + 24] * aw[24];
                ut[m * VV + w] = __float2half_rn(acc);
            }
        }
        __syncthreads();
        uint32_t* __restrict__ dst =
            (uint32_t*)(g_uh + (size_t)((p << 8) + ci) * NCOL + (size_t)n * CPN);
        const uint32_t* srcv = (const uint32_t*)ut;
        for (int i = t; i < CPN / 2; i += 256) dst[i] = srcv[i];
        __syncthreads();
    }
}

// ---------------- mega-GEMM: M=256 (all c), N=100 (4 LN groups), fused LN epilogue --
__global__ __launch_bounds__(256, 1) void gemm_kernel(const float* __restrict__ x,
                                                      const float* __restrict__ gamma,
                                                      const float* __restrict__ beta,
                                                      float* __restrict__ out) {
    extern __shared__ float dyns[];
    __half* sh = (__half*)dyns;
    __shared__ float red[8][8];
    __shared__ float totg[8];
    __shared__ float smean[4], srstd[4];

    const int tid = threadIdx.x;
    const int warp = tid >> 5;
    const int lane = tid & 31;
    const int grp = lane >> 2;
    const int tig = lane & 3;
    const int bx = blockIdx.x;            // 0..1199
    const int col0 = bx * BN;
    const int n = bx / 75;
    const int loc0 = (bx % 75) * BN;      // within-n column offset
    const int mf0 = (bx % 75) * 4;        // first frame of this CTA

    float acc[2][13][4];
#pragma unroll
    for (int i = 0; i < 2; ++i)
#pragma unroll
        for (int j = 0; j < 13; ++j)
#pragma unroll
            for (int r = 0; r < 4; ++r) acc[i][j][r] = 0.f;

    const uint32_t smem_base = smem_u32(dyns);

    // zero B pad columns (halves 100..111) in both stages; never rewritten
    for (int i = tid; i < 2 * 32 * 6; i += 256) {
        int s = i / 192, rem = i - s * 192;
        int kk = rem / 6, j = rem - kk * 6;
        *(uint32_t*)((char*)sh + ((size_t)s * STAGE_B) + (kk * BSHB + 100 + j * 2) * 2) = 0u;
    }

    auto load_chunk = [&](int s, int kc) {
        uint32_t As_b = smem_base + (uint32_t)s * STAGE_B;
        uint32_t Bs_b = As_b + ASTG * 2;
        const __half* Ag = g_Afrag + (size_t)kc * ASTG;
#pragma unroll
        for (int i = 0; i < 4; ++i) {
            int idx = i * 256 + tid;               // 0..1023
            cp16(As_b + idx * 16, Ag + idx * 8);
        }
        for (int i = tid; i < 800; i += 256) {
            int kk = i / 25;
            int cq = (i - kk * 25) * 4;            // halves
            cp8(Bs_b + (kk * BSHB + cq) * 2,
                g_uh + (size_t)(kc * 32 + kk) * NCOL + col0 + cq);
        }
        asm volatile("cp.async.commit_group;" ::: "memory");
    };

    load_chunk(0, 0);
    load_chunk(1, 1);

    for (int kc = 0; kc < NKC; ++kc) {
        if (kc + 1 < NKC) asm volatile("cp.async.wait_group 1;" ::: "memory");
        else              asm volatile("cp.async.wait_group 0;" ::: "memory");
        __syncthreads();

        const int s = kc & 1;
        const __half* As = sh + (size_t)s * STAGE_B / 2;
        const __half* Bs = As + ASTG;

#pragma unroll
        for (int k16 = 0; k16 < 2; ++k16) {
            uint4 a0 = *(const uint4*)(As + (((warp * 2 + k16) * 2 + 0) << 8) + lane * 8);
            uint4 a1 = *(const uint4*)(As + (((warp * 2 + k16) * 2 + 1) << 8) + lane * 8);
#pragma unroll
            for (int fn = 0; fn < 13; ++fn) {
                int nn = fn * 8 + grp;
                const __half* bp = Bs + (k16 * 16 + 2 * tig) * BSHB + nn;
                uint32_t lo0 = *(const unsigned short*)bp;
                uint32_t hi0 = *(const unsigned short*)(bp + BSHB);
                uint32_t b0 = lo0 | (hi0 << 16);
                uint32_t lo1 = *(const unsigned short*)(bp + 8 * BSHB);
                uint32_t hi1 = *(const unsigned short*)(bp + 9 * BSHB);
                uint32_t b1 = lo1 | (hi1 << 16);
                mma_f16(acc[0][fn], a0.x, a0.y, a0.z, a0.w, b0, b1);
                mma_f16(acc[1][fn], a1.x, a1.y, a1.z, a1.w, b0, b1);
            }
        }
        __syncthreads();
        if (kc + 2 < NKC) load_chunk(s, kc + 2);
    }
    __syncthreads();   // all mma done; stages can be overlaid by Cs

    // stage z + bias into Cs[e][c], e = local col 0..99, stride 261
    float* Cs = dyns;
#pragma unroll
    for (int fm = 0; fm < 2; ++fm)
#pragma unroll
        for (int fn = 0; fn < 13; ++fn)
#pragma unroll
            for (int r = 0; r < 4; ++r) {
                int nn = fn * 8 + 2 * tig + (r & 1);
                if (nn < BN) {
                    int c = warp * 32 + fm * 16 + grp + ((r & 2) ? 8 : 0);
                    int g = nn / 25;
                    int w = nn - g * 25;
                    int mf = mf0 + g;
                    float cnt = (float)((mf + 1 < 9) ? (mf + 1) : 9);
                    Cs[nn * CS_STRIDE + c] = acc[fm][fn][r] + cnt * g_bias2[c * VV + w];
                }
            }
    __syncthreads();

    // LN stats: thread = channel c; 4 groups
    {
        const int c = tid;
        float s[4], s2[4];
#pragma unroll
        for (int g = 0; g < 4; ++g) { s[g] = 0.f; s2[g] = 0.f; }
#pragma unroll
        for (int g = 0; g < 4; ++g)
            for (int w = 0; w < 25; ++w) {
                float v = Cs[(g * 25 + w) * CS_STRIDE + c];
                s[g] += v;
                s2[g] += v * v;
            }
#pragma unroll
        for (int g = 0; g < 4; ++g)
#pragma unroll
            for (int off = 16; off > 0; off >>= 1) {
                s[g]  += __shfl_down_sync(0xffffffffu, s[g],  off);
                s2[g] += __shfl_down_sync(0xffffffffu, s2[g], off);
            }
        if (lane == 0) {
#pragma unroll
            for (int g = 0; g < 4; ++g) { red[warp][g] = s[g]; red[warp][g + 4] = s2[g]; }
        }
    }
    __syncthreads();
    if (tid < 8) {
        float t = 0.f;
#pragma unroll
        for (int w = 0; w < 8; ++w) t += red[w][tid];
        totg[tid] = t;
    }
    __syncthreads();
    if (tid < 4) {
        const float inv = 1.f / 6400.f;
        float mean = totg[tid] * inv;
        float var = totg[tid + 4] * inv - mean * mean;
        smean[tid] = mean;
        srstd[tid] = rsqrtf(var + 1e-5f);
    }
    __syncthreads();

    // apply LN + gamma/beta + relu, in place in Cs
    {
        const int c = tid;
        const float* gm = gamma + c * VV;
        const float* bt = beta + c * VV;
#pragma unroll
        for (int g = 0; g < 4; ++g) {
            float mean = smean[g], rstd = srstd[g];
            for (int w = 0; w < 25; ++w) {
                int e = g * 25 + w;
                float z = Cs[e * CS_STRIDE + c];
                float yv = (z - mean) * rstd * gm[w] + bt[w];
                Cs[e * CS_STRIDE + c] = fmaxf(yv, 0.f);
            }
        }
    }
    __syncthreads();

    // residual + final relu, coalesced float4 on (m,v) dim
    // out/x offset: (n*256 + c)*7500 + loc0 + e   (loc0 % 4 == 0, 7500 % 4 == 0)
    for (int i = 0; i < 25; ++i) {
        int idx = i * 256 + tid;          // 0..6399
        int c = idx / 25;
        int j = idx - c * 25;             // float4 index within the 100 cols
        size_t base = ((size_t)(n * CIN + c)) * CPN + loc0 + j * 4;
        float4 xv = *(const float4*)(x + base);
        int e = j * 4;
        float4 yv;
        yv.x = fmaxf(Cs[(e + 0) * CS_STRIDE + c] + xv.x, 0.f);
        yv.y = fmaxf(Cs[(e + 1) * CS_STRIDE + c] + xv.y, 0.f);
        yv.z = fmaxf(Cs[(e + 2) * CS_STRIDE + c] + xv.z, 0.f);
        yv.w = fmaxf(Cs[(e + 3) * CS_STRIDE + c] + xv.w, 0.f);
        *(float4*)(out + base) = yv;
    }
}

// ---------------------------------------------------------------------------
extern "C" void kernel_launch(void* const* d_in, const int* in_sizes, int n_in,
                              void* d_out, int out_size) {
    const float* x      = (const float*)d_in[0];
    const float* A      = (const float*)d_in[1];
    const float* conv_w = (const float*)d_in[2];
    const float* conv_b = (const float*)d_in[3];
    const float* gamma  = (const float*)d_in[4];
    const float* beta   = (const float*)d_in[5];
    const float* ei     = (const float*)d_in[6];
    float* out = (float*)d_out;

    const int USMEM = LL * 28 * 4 + CPN * 2;   // 48600 bytes
    cudaFuncSetAttribute(gemm_kernel, cudaFuncAttributeMaxDynamicSharedMemorySize, GEMM_SMEM);
    cudaFuncSetAttribute(u_kernel, cudaFuncAttributeMaxDynamicSharedMemorySize, USMEM);

    prep_kernel<<<(COUT * KDIM + 255) / 256, 256>>>(A, conv_w, conv_b, ei);

    dim3 gu(CIN, NB);
    u_kernel<<<gu, 256, USMEM>>>(x);

    gemm_kernel<<<NCOL / BN, 256, GEMM_SMEM>>>(x, gamma, beta, out);
}

// round 8
// speedup vs baseline: 2.8241x; 1.1192x over previous
#include <cuda_runtime.h>
#include <cuda_fp16.h>
#include <cstdint>

#define NB 16
#define CIN 256
#define LL 300
#define VV 25
#define PP 3
#define COUT 256
#define NCOL 120000
#define CPN 7500
#define KDIM 768
#define NKC 24            // K chunks of 32

#define BN 100            // 4 LN-frame groups per CTA
#define BSHB 120          // halves per B smem row (padded, LDSM bank-friendly)
#define ASTG 8192         // A halves per chunk
#define STAGE_B (ASTG * 2 + 32 * BSHB * 2)      // 24064 bytes per stage
#define NSTAGE 4
#define CS_STRIDE 261
#define GEMM_SMEM (BN * CS_STRIDE * 4)          // 104400 B (> 4*STAGE_B = 96256)

__device__ __half g_uh[(size_t)KDIM * NCOL];    // [k=(p,ci)][col] 184 MB
__device__ __half g_Afrag[COUT * KDIM];         // fp16 fragment-ordered Wall
__device__ float g_Aw[PP * VV * VV];
__device__ float g_bias2[COUT * VV];

__device__ __forceinline__ void cp16(uint32_t dst, const void* src) {
    asm volatile("cp.async.cg.shared.global [%0], [%1], 16;" :: "r"(dst), "l"(src));
}
__device__ __forceinline__ void cp8(uint32_t dst, const void* src) {
    asm volatile("cp.async.ca.shared.global [%0], [%1], 8;" :: "r"(dst), "l"(src));
}
__device__ __forceinline__ uint32_t smem_u32(const void* p) {
    uint32_t a;
    asm("{ .reg .u64 t; cvta.to.shared.u64 t, %1; cvt.u32.u64 %0, t; }" : "=r"(a) : "l"(p));
    return a;
}
__device__ __forceinline__ void mma_f16(float* d, uint32_t a0, uint32_t a1, uint32_t a2,
                                        uint32_t a3, uint32_t b0, uint32_t b1) {
    asm volatile(
        "mma.sync.aligned.m16n8k16.row.col.f32.f16.f16.f32 "
        "{%0,%1,%2,%3}, {%4,%5,%6,%7}, {%8,%9}, {%0,%1,%2,%3};"
        : "+f"(d[0]), "+f"(d[1]), "+f"(d[2]), "+f"(d[3])
        : "r"(a0), "r"(a1), "r"(a2), "r"(a3), "r"(b0), "r"(b1));
}
#define LDSM_X4_T(r0, r1, r2, r3, addr) \
    asm volatile("ldmatrix.sync.aligned.m8n8.x4.trans.shared.b16 {%0,%1,%2,%3}, [%4];" \
                 : "=r"(r0), "=r"(r1), "=r"(r2), "=r"(r3) : "r"(addr))

// ---------------- prep: fp16 A fragments (M256 x 8-warp tiling), Aw, bias2 ---------
__global__ __launch_bounds__(256) void prep_kernel(const float* __restrict__ A,
                                                   const float* __restrict__ conv_w,
                                                   const float* __restrict__ conv_b,
                                                   const float* __restrict__ ei) {
    int e = blockIdx.x * 256 + threadIdx.x;
    if (e < COUT * KDIM) {
        int r = e / KDIM;
        int k = e - r * KDIM;
        int p = k >> 8, ci = k & 255;
        float w = conv_w[((p << 8) + r) * CIN + ci];
        int wm = r >> 5, fm = (r >> 4) & 1, rr = r & 15;
        int kchunk = k >> 5, k16 = (k >> 4) & 1, kkk = k & 15;
        int reg = (rr >> 3) | ((kkk >> 3) << 1);
        int lane = ((rr & 7) << 2) | ((kkk & 7) >> 1);
        int hl = kkk & 1;
        size_t off = ((((size_t)(kchunk * 8 + wm) * 2 + k16) * 2 + fm) * 256)
                     + lane * 8 + reg * 2 + hl;
        g_Afrag[off] = __float2half_rn(w);
    }
    if (e < PP * VV * VV) g_Aw[e] = A[e] * ei[e];
    if (e < COUT * VV) {
        int c = e / VV, w = e - (e / VV) * VV;
        float s = 0.f;
        for (int p = 0; p < PP; ++p) {
            float b = conv_b[(p << 8) + c];
            for (int v = 0; v < VV; ++v) {
                int a = (p * VV + v) * VV + w;
                s += b * A[a] * ei[a];
            }
        }
        g_bias2[e] = s;
    }
}

// ---------------- u kernel: window sum + graph agg, fp16 smem-staged stores --------
__global__ __launch_bounds__(256) void u_kernel(const float* __restrict__ x) {
    extern __shared__ __align__(16) float us[];
    float* xt = us;                           // 300 * 28 floats
    __half* ut = (__half*)(us + LL * 28);     // 7500 halves
    const int n = blockIdx.y;
    const int ci = blockIdx.x;
    const float* __restrict__ xr = x + ((size_t)(n * CIN + ci)) * CPN;
    const int t = threadIdx.x;

    if (t < 250) {
        int v = t % 25;
        int mi = t / 25;
        int m0 = mi * 30;
        float s = 0.f;
        int lstart = m0 - 8; if (lstart < 0) lstart = 0;
        for (int l = lstart; l < m0; ++l) s += xr[l * VV + v];
        for (int m = m0; m < m0 + 30; ++m) {
            s += xr[m * VV + v];
            xt[m * 28 + v] = s;
            if (m >= 8) s -= xr[(m - 8) * VV + v];
        }
    }
    __syncthreads();

    const int w = t & 31;
    const int mg = t >> 5;
    float aw[25];
    for (int p = 0; p < PP; ++p) {
        if (w < 25) {
#pragma unroll
            for (int v = 0; v < 25; ++v) aw[v] = g_Aw[(p * VV + v) * VV + w];
            for (int m = mg; m < LL; m += 8) {
                const float4* xv4 = (const float4*)(xt + m * 28);
                float acc = 0.f;
#pragma unroll
                for (int q = 0; q < 6; ++q) {
                    float4 xv = xv4[q];
                    acc += xv.x * aw[4 * q + 0];
                    acc += xv.y * aw[4 * q + 1];
                    acc += xv.z * aw[4 * q + 2];
                    acc += xv.w * aw[4 * q + 3];
                }
                acc += xt[m * 28 + 24] * aw[24];
                ut[m * VV + w] = __float2half_rn(acc);
            }
        }
        __syncthreads();
        uint32_t* __restrict__ dst =
            (uint32_t*)(g_uh + (size_t)((p << 8) + ci) * NCOL + (size_t)n * CPN);
        const uint32_t* srcv = (const uint32_t*)ut;
        for (int i = t; i < CPN / 2; i += 256) dst[i] = srcv[i];
        __syncthreads();
    }
}

// ---------------- mega-GEMM: 512 threads, ldmatrix B frags, 4-stage pipe ----------
__global__ __launch_bounds__(512, 1) void gemm_kernel(const float* __restrict__ x,
                                                      const float* __restrict__ gamma,
                                                      const float* __restrict__ beta,
                                                      float* __restrict__ out) {
    extern __shared__ float dyns[];
    __half* sh = (__half*)dyns;
    __shared__ float red[16][4];
    __shared__ float smean[4], srstd[4];

    const int tid = threadIdx.x;
    const int warp = tid >> 5;
    const int lane = tid & 31;
    const int wm = warp >> 1;            // 0..7 -> c0 = wm*32
    const int wn = warp & 1;             // 0..1 -> fn base = wn*7
    const int grp = lane >> 2;
    const int tig = lane & 3;
    const int fnc = wn ? 6 : 7;
    const int bx = blockIdx.x;           // 0..1199
    const int col0 = bx * BN;
    const int n = bx / 75;
    const int loc0 = (bx % 75) * BN;
    const int mf0 = (bx % 75) * 4;

    float acc[2][7][4];
#pragma unroll
    for (int i = 0; i < 2; ++i)
#pragma unroll
        for (int j = 0; j < 7; ++j)
#pragma unroll
            for (int r = 0; r < 4; ++r) acc[i][j][r] = 0.f;

    const uint32_t smem_base = smem_u32(dyns);

    // zero B pad columns (halves 100..119) in all stages; never touched by cp.async
    for (int i = tid; i < NSTAGE * 32 * 10; i += 512) {
        int s = i / 320, rem = i - s * 320;
        int kk = rem / 10, j = rem - kk * 10;
        *(uint32_t*)((char*)sh + (size_t)s * STAGE_B + ASTG * 2
                     + (kk * BSHB + 100) * 2 + j * 4) = 0u;
    }

    auto load_chunk = [&](int s, int kc) {
        uint32_t As_b = smem_base + (uint32_t)s * STAGE_B;
        uint32_t Bs_b = As_b + ASTG * 2;
        const __half* Ag = g_Afrag + (size_t)kc * ASTG;
#pragma unroll
        for (int i = 0; i < 2; ++i) {
            int idx = i * 512 + tid;               // 0..1023
            cp16(As_b + idx * 16, Ag + idx * 8);
        }
        {
            int i = tid;                           // 0..511 (need 800)
            int kk = i / 25, cq = (i - kk * 25) * 4;
            cp8(Bs_b + (kk * BSHB + cq) * 2,
                g_uh + (size_t)(kc * 32 + kk) * NCOL + col0 + cq);
            i = tid + 512;
            if (i < 800) {
                kk = i / 25; cq = (i - kk * 25) * 4;
                cp8(Bs_b + (kk * BSHB + cq) * 2,
                    g_uh + (size_t)(kc * 32 + kk) * NCOL + col0 + cq);
            }
        }
        asm volatile("cp.async.commit_group;" ::: "memory");
    };

    load_chunk(0, 0);
    load_chunk(1, 1);
    load_chunk(2, 2);

    // ldmatrix per-lane addressing precompute
    const int matid = lane >> 3;
    const int mrow = lane & 7;
    const int lds_row = (matid & 1) * 8 + mrow;              // within k16 block
    const int lds_fn0 = wn * 7 + (matid >> 1);               // + 2*j at issue

    for (int kc = 0; kc < NKC; ++kc) {
        if (kc < NKC - 2)      asm volatile("cp.async.wait_group 2;" ::: "memory");
        else if (kc == NKC - 2) asm volatile("cp.async.wait_group 1;" ::: "memory");
        else                   asm volatile("cp.async.wait_group 0;" ::: "memory");
        __syncthreads();

        if (kc + 3 < NKC) load_chunk((kc + 3) & 3, kc + 3);

        const int s = kc & 3;
        const __half* As = sh + (size_t)s * STAGE_B / 2;
        const uint32_t Bs_b = smem_base + (uint32_t)s * STAGE_B + ASTG * 2;

#pragma unroll
        for (int k16 = 0; k16 < 2; ++k16) {
            uint4 a0 = *(const uint4*)(As + (((wm * 2 + k16) * 2 + 0) << 8) + lane * 8);
            uint4 a1 = *(const uint4*)(As + (((wm * 2 + k16) * 2 + 1) << 8) + lane * 8);
            uint32_t bfr[16];
            uint32_t baddr = Bs_b + ((k16 * 16 + lds_row) * BSHB + lds_fn0 * 8) * 2;
#pragma unroll
            for (int j = 0; j < 4; ++j) {
                if (wn == 0 || j < 3)
                    LDSM_X4_T(bfr[4 * j], bfr[4 * j + 1], bfr[4 * j + 2], bfr[4 * j + 3],
                              baddr + j * 32);   // +2 fn = 16 halves = 32 bytes
            }
#pragma unroll
            for (int f = 0; f < 7; ++f) {
                if (f < fnc) {
                    mma_f16(acc[0][f], a0.x, a0.y, a0.z, a0.w, bfr[2 * f], bfr[2 * f + 1]);
                    mma_f16(acc[1][f], a1.x, a1.y, a1.z, a1.w, bfr[2 * f], bfr[2 * f + 1]);
                }
            }
        }
        __syncthreads();
    }

    // ---------- epilogue: stage z + bias into Cs[e][c] ----------
    float* Cs = dyns;
#pragma unroll
    for (int fm = 0; fm < 2; ++fm)
#pragma unroll
        for (int f = 0; f < 7; ++f)
#pragma unroll
            for (int r = 0; r < 4; ++r) {
                int nn = wn * 56 + f * 8 + 2 * tig + (r & 1);
                if (f < fnc && nn < BN) {
                    int c = wm * 32 + fm * 16 + grp + ((r & 2) ? 8 : 0);
                    int g = nn / 25;
                    int w = nn - g * 25;
                    int mf = mf0 + g;
                    float cnt = (float)((mf + 1 < 9) ? (mf + 1) : 9);
                    Cs[nn * CS_STRIDE + c] = acc[fm][f][r] + cnt * g_bias2[c * VV + w];
                }
            }
    __syncthreads();

    // ---------- LN stats: tid<256 -> groups 0,1 ; tid>=256 -> groups 2,3 ----------
    {
        const int half = tid >> 8;
        const int c = tid & 255;
        float s0 = 0.f, q0 = 0.f, s1 = 0.f, q1 = 0.f;
        const float* c0p = Cs + (half * 2 + 0) * 25 * CS_STRIDE + c;
        const float* c1p = Cs + (half * 2 + 1) * 25 * CS_STRIDE + c;
#pragma unroll
        for (int w = 0; w < 25; ++w) {
            float v0 = c0p[w * CS_STRIDE];
            float v1 = c1p[w * CS_STRIDE];
            s0 += v0; q0 += v0 * v0;
            s1 += v1; q1 += v1 * v1;
        }
#pragma unroll
        for (int off = 16; off > 0; off >>= 1) {
            s0 += __shfl_down_sync(0xffffffffu, s0, off);
            q0 += __shfl_down_sync(0xffffffffu, q0, off);
            s1 += __shfl_down_sync(0xffffffffu, s1, off);
            q1 += __shfl_down_sync(0xffffffffu, q1, off);
        }
        if (lane == 0) {
            red[warp][0] = s0; red[warp][1] = q0;
            red[warp][2] = s1; red[warp][3] = q1;
        }
    }
    __syncthreads();
    if (tid < 4) {
        int hw = (tid >> 1) * 8;          // warps 0-7 for groups 0,1; 8-15 for 2,3
        int sel = (tid & 1) * 2;
        float s = 0.f, q = 0.f;
#pragma unroll
        for (int w = 0; w < 8; ++w) { s += red[hw + w][sel]; q += red[hw + w][sel + 1]; }
        const float inv = 1.f / 6400.f;
        float mean = s * inv;
        float var = q * inv - mean * mean;
        smean[tid] = mean;
        srstd[tid] = rsqrtf(var + 1e-5f);
    }
    __syncthreads();

    // ---------- apply LN + gamma/beta + relu in Cs ----------
    {
        const int half = tid >> 8;
        const int c = tid & 255;
        const float* gm = gamma + c * VV;
        const float* bt = beta + c * VV;
#pragma unroll
        for (int gg = 0; gg < 2; ++gg) {
            int g = half * 2 + gg;
            float mean = smean[g], rstd = srstd[g];
            float* cp = Cs + g * 25 * CS_STRIDE + c;
            for (int w = 0; w < 25; ++w) {
                float z = cp[w * CS_STRIDE];
                float yv = (z - mean) * rstd * gm[w] + bt[w];
                cp[w * CS_STRIDE] = fmaxf(yv, 0.f);
            }
        }
    }
    __syncthreads();

    // ---------- residual + final relu, coalesced float4 ----------
    for (int i = 0; i < 13; ++i) {
        int idx = i * 512 + tid;          // 0..6399
        if (idx < 6400) {
            int c = idx / 25;
            int j = idx - c * 25;
            size_t base = ((size_t)(n * CIN + c)) * CPN + loc0 + j * 4;
            float4 xv = *(const float4*)(x + base);
            int e = j * 4;
            float4 yv;
            yv.x = fmaxf(Cs[(e + 0) * CS_STRIDE + c] + xv.x, 0.f);
            yv.y = fmaxf(Cs[(e + 1) * CS_STRIDE + c] + xv.y, 0.f);
            yv.z = fmaxf(Cs[(e + 2) * CS_STRIDE + c] + xv.z, 0.f);
            yv.w = fmaxf(Cs[(e + 3) * CS_STRIDE + c] + xv.w, 0.f);
            *(float4*)(out + base) = yv;
        }
    }
}

// ---------------------------------------------------------------------------
extern "C" void kernel_launch(void* const* d_in, const int* in_sizes, int n_in,
                              void* d_out, int out_size) {
    const float* x      = (const float*)d_in[0];
    const float* A      = (const float*)d_in[1];
    const float* conv_w = (const float*)d_in[2];
    const float* conv_b = (const float*)d_in[3];
    const float* gamma  = (const float*)d_in[4];
    const float* beta   = (const float*)d_in[5];
    const float* ei     = (const float*)d_in[6];
    float* out = (float*)d_out;

    const int USMEM = LL * 28 * 4 + CPN * 2;   // 48600 bytes
    cudaFuncSetAttribute(gemm_kernel, cudaFuncAttributeMaxDynamicSharedMemorySize, GEMM_SMEM);
    cudaFuncSetAttribute(u_kernel, cudaFuncAttributeMaxDynamicSharedMemorySize, USMEM);

    prep_kernel<<<(COUT * KDIM + 255) / 256, 256>>>(A, conv_w, conv_b, ei);

    dim3 gu(CIN, NB);
    u_kernel<<<gu, 256, USMEM>>>(x);

    gemm_kernel<<<NCOL / BN, 512, GEMM_SMEM>>>(x, gamma, beta, out);
}